// round 13
// baseline (speedup 1.0000x reference)
#include <cuda_runtime.h>
#include <cuda_fp16.h>
#include <math.h>
#include <stdint.h>

constexpr int B_    = 2;
constexpr int NQ    = 2048;
constexpr int NKV   = 2048;
constexpr int D     = 1024;
constexpr int INNER = 1024;
constexpr int HEADS = 16;
constexpr int DIMH  = 64;

constexpr int ROWS = B_ * NQ; // 4096
constexpr float SCALE_LOG2E = 0.125f * 1.4426950408889634f;

// Scratch (allocation-free rule: __device__ globals)
__device__ __half g_Q[ROWS * INNER];
__device__ __half g_K[ROWS * INNER];
__device__ __half g_V[ROWS * INNER];
__device__ __half g_A[ROWS * INNER];
__device__ __half g_PA[ROWS * D];
__device__ __half g_PX[ROWS * D];
__device__ __half g_WQ[D * INNER];   // transposed weights [N][K]
__device__ __half g_WK[D * INNER];
__device__ __half g_WV[D * INNER];
__device__ __half g_WO[INNER * D];

// ---------------------------------------------------------------------------
// helpers
// ---------------------------------------------------------------------------
__device__ __forceinline__ void cp_async16(void* dst, const void* src) {
    uint32_t s = (uint32_t)__cvta_generic_to_shared(dst);
    asm volatile("cp.async.cg.shared.global [%0], [%1], 16;\n" :: "r"(s), "l"(src));
}
__device__ __forceinline__ void cp_commit() { asm volatile("cp.async.commit_group;\n"); }

__device__ __forceinline__ float ex2(float x) {
    float r; asm("ex2.approx.ftz.f32 %0, %1;" : "=f"(r) : "f"(x)); return r;
}
__device__ __forceinline__ uint32_t pack2(float lo, float hi) {
    uint32_t r;
    asm("cvt.rn.f16x2.f32 %0, %1, %2;" : "=r"(r) : "f"(hi), "f"(lo));
    return r;
}

__device__ __forceinline__ void mma_f16(float* c, const uint32_t* a, uint32_t b0, uint32_t b1) {
    asm volatile(
        "mma.sync.aligned.m16n8k16.row.col.f32.f16.f16.f32 "
        "{%0,%1,%2,%3}, {%4,%5,%6,%7}, {%8,%9}, {%0,%1,%2,%3};\n"
        : "+f"(c[0]), "+f"(c[1]), "+f"(c[2]), "+f"(c[3])
        : "r"(a[0]), "r"(a[1]), "r"(a[2]), "r"(a[3]), "r"(b0), "r"(b1));
}

__device__ __forceinline__ void ldmx4(uint32_t& r0, uint32_t& r1, uint32_t& r2, uint32_t& r3,
                                      const void* p) {
    uint32_t a = (uint32_t)__cvta_generic_to_shared(p);
    asm volatile("ldmatrix.sync.aligned.m8n8.x4.shared.b16 {%0,%1,%2,%3}, [%4];"
                 : "=r"(r0), "=r"(r1), "=r"(r2), "=r"(r3) : "r"(a));
}
__device__ __forceinline__ void ldmx4_trans(uint32_t& r0, uint32_t& r1, uint32_t& r2, uint32_t& r3,
                                            const void* p) {
    uint32_t a = (uint32_t)__cvta_generic_to_shared(p);
    asm volatile("ldmatrix.sync.aligned.m8n8.x4.trans.shared.b16 {%0,%1,%2,%3}, [%4];"
                 : "=r"(r0), "=r"(r1), "=r"(r2), "=r"(r3) : "r"(a));
}
__device__ __forceinline__ void ldmx2_trans(uint32_t& r0, uint32_t& r1, const void* p) {
    uint32_t a = (uint32_t)__cvta_generic_to_shared(p);
    asm volatile("ldmatrix.sync.aligned.m8n8.x2.trans.shared.b16 {%0,%1}, [%2];"
                 : "=r"(r0), "=r"(r1) : "r"(a));
}

// ---------------------------------------------------------------------------
// prep kernels
// ---------------------------------------------------------------------------
__global__ void cvth4(__half* __restrict__ d0, const float4* __restrict__ s0,
                      __half* __restrict__ d1, const float4* __restrict__ s1,
                      int n4, int stride) {
    const int base = blockIdx.x * blockDim.x + threadIdx.x;
    const float4* s = blockIdx.y ? s1 : s0;
    __half* d = blockIdx.y ? d1 : d0;
    float4 v[4];
#pragma unroll
    for (int k = 0; k < 4; k++) {
        const int i = base + k * stride;
        v[k] = s[i];
    }
#pragma unroll
    for (int k = 0; k < 4; k++) {
        const int i = base + k * stride;
        uint2 o;
        o.x = pack2(v[k].x, v[k].y);
        o.y = pack2(v[k].z, v[k].w);
        *reinterpret_cast<uint2*>(d + 4 * (size_t)i) = o;
    }
}

__global__ void transpose_cvt4(__half* __restrict__ d0, const float* __restrict__ s0,
                               __half* __restrict__ d1, const float* __restrict__ s1,
                               __half* __restrict__ d2, const float* __restrict__ s2,
                               __half* __restrict__ d3, const float* __restrict__ s3) {
    __shared__ float t[32][33];
    const int z = blockIdx.z;
    const float* src = (z == 0) ? s0 : (z == 1) ? s1 : (z == 2) ? s2 : s3;
    __half* dst = (z == 0) ? d0 : (z == 1) ? d1 : (z == 2) ? d2 : d3;
    const int n0 = blockIdx.x * 32;
    const int k0 = blockIdx.y * 32;
    const int tx = threadIdx.x, ty = threadIdx.y;
#pragma unroll
    for (int i = 0; i < 4; i++)
        t[ty + i * 8][tx] = src[(size_t)(k0 + ty + i * 8) * 1024 + n0 + tx];
    __syncthreads();
#pragma unroll
    for (int i = 0; i < 4; i++)
        dst[(size_t)(n0 + ty + i * 8) * 1024 + k0 + tx] = __float2half_rn(t[tx][ty + i * 8]);
}

// ---------------------------------------------------------------------------
// fp16 GEMM (unchanged): 4-stage cp.async, ldmatrix frag loads.
// ---------------------------------------------------------------------------
constexpr int HG_LD = 40;
constexpr int HG_TILE = 128 * HG_LD;
constexpr int HG_STAGES = 4;
constexpr int HG_SMEM = HG_STAGES * 2 * HG_TILE * 2; // 81920 B

template <bool QKV, bool HALF_OUT, bool BIAS>
__global__ __launch_bounds__(256, 2)
void hgemm(const __half* __restrict__ A0, const __half* __restrict__ W0, void* __restrict__ C0,
           const __half* __restrict__ A1, const __half* __restrict__ W1, void* __restrict__ C1,
           const __half* __restrict__ A2, const __half* __restrict__ W2, void* __restrict__ C2,
           const float* __restrict__ bias, int M, int N, int K, float oscale0) {
    extern __shared__ __half sh[];

    const __half* A = A0; const __half* WT = W0; void* Cv = C0;
    float oscale = oscale0;
    if (QKV) {
        const int z = blockIdx.z;
        if (z == 1) { A = A1; WT = W1; Cv = C1; oscale = 1.0f; }
        else if (z == 2) { A = A2; WT = W2; Cv = C2; oscale = 1.0f; }
    }

    const int tid  = threadIdx.x;
    const int wid  = tid >> 5;
    const int lane = tid & 31;
    const int g    = lane >> 2;
    const int tig  = lane & 3;
    const int wm = wid >> 1;
    const int wn = wid & 1;
    const int bm0 = blockIdx.y * 128;
    const int bn0 = blockIdx.x * 128;
    const int lmr = lane & 15;
    const int lmc = (lane >> 4) * 8;

    float acc[2][8][4];
#pragma unroll
    for (int mi = 0; mi < 2; mi++)
#pragma unroll
        for (int nb = 0; nb < 8; nb++)
#pragma unroll
            for (int e = 0; e < 4; e++) acc[mi][nb][e] = 0.0f;

    auto load_tiles = [&](int buf, int k0) {
#pragma unroll
        for (int i = 0; i < 2; i++) {
            const int idx = tid + i * 256;
            const int r = idx >> 2, c = idx & 3;
            cp_async16(&sh[buf * 2 * HG_TILE + r * HG_LD + c * 8],
                       &A[(size_t)(bm0 + r) * K + k0 + c * 8]);
        }
#pragma unroll
        for (int i = 0; i < 2; i++) {
            const int idx = tid + i * 256;
            const int r = idx >> 2, c = idx & 3;
            cp_async16(&sh[buf * 2 * HG_TILE + HG_TILE + r * HG_LD + c * 8],
                       &WT[(size_t)(bn0 + r) * K + k0 + c * 8]);
        }
    };

    const int KT = K / 32;
    load_tiles(0, 0);  cp_commit();
    load_tiles(1, 32); cp_commit();
    load_tiles(2, 64); cp_commit();

    for (int t = 0; t < KT; t++) {
        const int buf = t & 3;
        asm volatile("cp.async.wait_group 2;\n");
        __syncthreads();
        if (t + 3 < KT) { load_tiles((t + 3) & 3, (t + 3) * 32); cp_commit(); }

        const __half* Ab = sh + buf * 2 * HG_TILE;
        const __half* Bb = Ab + HG_TILE;
#pragma unroll
        for (int ks = 0; ks < 2; ks++) {
            uint32_t a[2][4];
            uint32_t b[4][4];
#pragma unroll
            for (int mi = 0; mi < 2; mi++)
                ldmx4(a[mi][0], a[mi][1], a[mi][2], a[mi][3],
                      Ab + (wm * 32 + mi * 16 + lmr) * HG_LD + ks * 16 + lmc);
#pragma unroll
            for (int nbp = 0; nbp < 4; nbp++)
                ldmx4(b[nbp][0], b[nbp][1], b[nbp][2], b[nbp][3],
                      Bb + (wn * 64 + nbp * 16 + lmr) * HG_LD + ks * 16 + lmc);
#pragma unroll
            for (int nbp = 0; nbp < 4; nbp++)
#pragma unroll
                for (int mi = 0; mi < 2; mi++) {
                    mma_f16(acc[mi][2 * nbp],     a[mi], b[nbp][0], b[nbp][2]);
                    mma_f16(acc[mi][2 * nbp + 1], a[mi], b[nbp][1], b[nbp][3]);
                }
        }
    }

#pragma unroll
    for (int mi = 0; mi < 2; mi++) {
        const int row0 = bm0 + wm * 32 + mi * 16 + g;
#pragma unroll
        for (int nb = 0; nb < 8; nb++) {
            const int col = bn0 + wn * 64 + nb * 8 + 2 * tig;
            float c0 = acc[mi][nb][0] * oscale, c1 = acc[mi][nb][1] * oscale;
            float c2 = acc[mi][nb][2] * oscale, c3 = acc[mi][nb][3] * oscale;
            if (BIAS) {
                const float b0 = bias[col], b1 = bias[col + 1];
                c0 += b0; c1 += b1; c2 += b0; c3 += b1;
            }
            if (HALF_OUT) {
                __half* C = (__half*)Cv;
                *reinterpret_cast<uint32_t*>(&C[(size_t)row0 * N + col])       = pack2(c0, c1);
                *reinterpret_cast<uint32_t*>(&C[(size_t)(row0 + 8) * N + col]) = pack2(c2, c3);
            } else {
                float* C = (float*)Cv;
                *reinterpret_cast<float2*>(&C[(size_t)row0 * N + col])       = make_float2(c0, c1);
                *reinterpret_cast<float2*>(&C[(size_t)(row0 + 8) * N + col]) = make_float2(c2, c3);
            }
        }
    }
}

// ---------------------------------------------------------------------------
// fp16 flash attention v9: SINGLE-WAVE schedule.
//  - Q tile staged in smem (frees 32 regs) -> __launch_bounds__(128,4)
//    -> 4 blocks/SM, 592 slots >= 512 blocks: one wave (vs 2 waves / 58%).
//  - same proven math as attn5/round-9: 4 warps x 32 q-rows, unnormalized
//    fp32 ex2 softmax, ones-column mma row sums, 2-stage cp.async K/V.
// ---------------------------------------------------------------------------
constexpr int ALD = 72;                       // halves per K/V row (144B stride)
constexpr int ATILE = 64 * ALD;               // halves per K or V tile
constexpr int QLD = 72;                       // Q smem stride (halves)
constexpr int QS_HALVES = 128 * QLD;          // 9216
constexpr int ATT_SMEM = (QS_HALVES + 4 * ATILE) * 2;  // 55296 B
constexpr int AGRID9 = (NQ / 128) * HEADS * B_;        // 512

__global__ __launch_bounds__(128, 4)
void attn9(const __half* __restrict__ Q, const __half* __restrict__ K,
           const __half* __restrict__ V, __half* __restrict__ O) {
    extern __shared__ __half sh[];
    __half* Qs = sh;                 // [128][QLD]
    __half* KV = sh + QS_HALVES;     // [2 bufs][Ktile, Vtile]

    const int tid  = threadIdx.x;
    const int w    = tid >> 5;
    const int lane = tid & 31;
    const int g    = lane >> 2;
    const int tig  = lane & 3;
    const int lmr = lane & 15;
    const int lmc = (lane >> 4) * 8;

    const int qt = blockIdx.x & 15;
    const int hb = blockIdx.x >> 4;
    const int h  = hb & 15;
    const int b  = hb >> 4;
    const int q0 = qt * 128;

    // ones-pad init: V tiles' cols 64-71 = [1,0,...] in both buffers
    {
        const int buf = tid >> 6, r = tid & 63;
        uint4 ones = make_uint4(0x00003C00u, 0u, 0u, 0u);
        *reinterpret_cast<uint4*>(KV + (buf * 2 + 1) * ATILE + r * ALD + 64) = ones;
    }

    const __half* Qg = Q + (size_t)(b * NQ + q0) * INNER + h * DIMH;
    const __half* Kg = K + (size_t)(b * NKV) * INNER + h * DIMH;
    const __half* Vg = V + (size_t)(b * NKV) * INNER + h * DIMH;

    auto prefetch = [&](int buf, int j0) {
#pragma unroll
        for (int i = 0; i < 4; i++) {
            const int idx = tid + i * 128;
            const int r = idx >> 3, c = idx & 7;
            cp_async16(&KV[buf * 2 * ATILE + r * ALD + c * 8],
                       Kg + (size_t)(j0 + r) * INNER + c * 8);
        }
#pragma unroll
        for (int i = 0; i < 4; i++) {
            const int idx = tid + i * 128;
            const int r = idx >> 3, c = idx & 7;
            cp_async16(&KV[buf * 2 * ATILE + ATILE + r * ALD + c * 8],
                       Vg + (size_t)(j0 + r) * INNER + c * 8);
        }
    };

    // Q tile (128 x 64 halves) -> smem, plus first K/V tile, one group
#pragma unroll
    for (int i = 0; i < 8; i++) {
        const int idx = tid + i * 128;
        const int r = idx >> 3, c = idx & 7;
        cp_async16(&Qs[r * QLD + c * 8], Qg + (size_t)r * INNER + c * 8);
    }
    prefetch(0, 0);
    cp_commit();

    float oa0[8][4], oa1[8][4];
    float sum0[4] = {0.f, 0.f, 0.f, 0.f};
    float sum1[4] = {0.f, 0.f, 0.f, 0.f};
#pragma unroll
    for (int nb = 0; nb < 8; nb++)
#pragma unroll
        for (int e = 0; e < 4; e++) { oa0[nb][e] = 0.0f; oa1[nb][e] = 0.0f; }

    constexpr int NT = NKV / 64;
    for (int t = 0; t < NT; t++) {
        const int buf = t & 1;
        asm volatile("cp.async.wait_group 0;\n");
        __syncthreads();
        if (t + 1 < NT) { prefetch(buf ^ 1, (t + 1) * 64); cp_commit(); }

        const __half* Kb = KV + buf * 2 * ATILE;
        const __half* Vb = Kb + ATILE;

#pragma unroll
        for (int nbp = 0; nbp < 4; nbp++) {
            float s00[4] = {0.f,0.f,0.f,0.f}, s01[4] = {0.f,0.f,0.f,0.f};
            float s10[4] = {0.f,0.f,0.f,0.f}, s11[4] = {0.f,0.f,0.f,0.f};
#pragma unroll
            for (int kk = 0; kk < 4; kk++) {
                uint32_t b0, b1, b2, b3;
                ldmx4(b0, b1, b2, b3, Kb + (nbp * 16 + lmr) * ALD + kk * 16 + lmc);
                uint32_t qlo[4], qhi[4];
                ldmx4(qlo[0], qlo[1], qlo[2], qlo[3],
                      Qs + (w * 32 + lmr) * QLD + kk * 16 + lmc);
                ldmx4(qhi[0], qhi[1], qhi[2], qhi[3],
                      Qs + (w * 32 + 16 + lmr) * QLD + kk * 16 + lmc);
                mma_f16(s00, qlo, b0, b2);
                mma_f16(s01, qlo, b1, b3);
                mma_f16(s10, qhi, b0, b2);
                mma_f16(s11, qhi, b1, b3);
            }
            uint32_t pa0[4], pa1[4];
            pa0[0] = pack2(ex2(s00[0]), ex2(s00[1]));
            pa0[1] = pack2(ex2(s00[2]), ex2(s00[3]));
            pa0[2] = pack2(ex2(s01[0]), ex2(s01[1]));
            pa0[3] = pack2(ex2(s01[2]), ex2(s01[3]));
            pa1[0] = pack2(ex2(s10[0]), ex2(s10[1]));
            pa1[1] = pack2(ex2(s10[2]), ex2(s10[3]));
            pa1[2] = pack2(ex2(s11[0]), ex2(s11[1]));
            pa1[3] = pack2(ex2(s11[2]), ex2(s11[3]));

#pragma unroll
            for (int j = 0; j < 4; j++) {
                uint32_t b0, b1, b2, b3;
                ldmx4_trans(b0, b1, b2, b3, Vb + (nbp * 16 + lmr) * ALD + j * 16 + lmc);
                mma_f16(oa0[2 * j],     pa0, b0, b1);
                mma_f16(oa0[2 * j + 1], pa0, b2, b3);
                mma_f16(oa1[2 * j],     pa1, b0, b1);
                mma_f16(oa1[2 * j + 1], pa1, b2, b3);
            }
            {
                uint32_t c0, c1;
                ldmx2_trans(c0, c1, Vb + (nbp * 16 + lmr) * ALD + 64);
                mma_f16(sum0, pa0, c0, c1);
                mma_f16(sum1, pa1, c0, c1);
            }
        }
    }

    // extract row sums (col 64 -> tig==0 lanes: c[0]=row g, c[2]=row g+8)
    const int src = lane & 28;
    const float inv00 = 1.0f / __shfl_sync(0xffffffffu, sum0[0], src);
    const float inv01 = 1.0f / __shfl_sync(0xffffffffu, sum0[2], src);
    const float inv10 = 1.0f / __shfl_sync(0xffffffffu, sum1[0], src);
    const float inv11 = 1.0f / __shfl_sync(0xffffffffu, sum1[2], src);

    const int r0 = q0 + w * 32 + g;
    __half* O0 = O + (size_t)(b * NQ + r0) * INNER + h * DIMH;
    __half* O1 = O0 + 8 * (size_t)INNER;
    __half* O2 = O0 + 16 * (size_t)INNER;
    __half* O3 = O0 + 24 * (size_t)INNER;
#pragma unroll
    for (int nb = 0; nb < 8; nb++) {
        *reinterpret_cast<uint32_t*>(O0 + nb * 8 + 2 * tig) =
            pack2(oa0[nb][0] * inv00, oa0[nb][1] * inv00);
        *reinterpret_cast<uint32_t*>(O1 + nb * 8 + 2 * tig) =
            pack2(oa0[nb][2] * inv01, oa0[nb][3] * inv01);
        *reinterpret_cast<uint32_t*>(O2 + nb * 8 + 2 * tig) =
            pack2(oa1[nb][0] * inv10, oa1[nb][1] * inv10);
        *reinterpret_cast<uint32_t*>(O3 + nb * 8 + 2 * tig) =
            pack2(oa1[nb][2] * inv11, oa1[nb][3] * inv11);
    }
}

// ---------------------------------------------------------------------------
extern "C" void kernel_launch(void* const* d_in, const int* in_sizes, int n_in,
                              void* d_out, int out_size) {
    const float* patch = (const float*)d_in[0];
    const float* pixel = (const float*)d_in[1];
    const float* Wq    = (const float*)d_in[2];
    const float* Wk    = (const float*)d_in[3];
    const float* Wv    = (const float*)d_in[4];
    const float* Wo    = (const float*)d_in[5];
    const float* bo    = (const float*)d_in[6];
    float* out = (float*)d_out;

    __half *pQ, *pK, *pV, *pA, *pPA, *pPX, *pWQ, *pWK, *pWV, *pWO;
    cudaGetSymbolAddress((void**)&pQ,  g_Q);
    cudaGetSymbolAddress((void**)&pK,  g_K);
    cudaGetSymbolAddress((void**)&pV,  g_V);
    cudaGetSymbolAddress((void**)&pA,  g_A);
    cudaGetSymbolAddress((void**)&pPA, g_PA);
    cudaGetSymbolAddress((void**)&pPX, g_PX);
    cudaGetSymbolAddress((void**)&pWQ, g_WQ);
    cudaGetSymbolAddress((void**)&pWK, g_WK);
    cudaGetSymbolAddress((void**)&pWV, g_WV);
    cudaGetSymbolAddress((void**)&pWO, g_WO);

    cudaFuncSetAttribute((const void*)hgemm<true, true, false>,
                         cudaFuncAttributeMaxDynamicSharedMemorySize, HG_SMEM);
    cudaFuncSetAttribute((const void*)hgemm<false, false, true>,
                         cudaFuncAttributeMaxDynamicSharedMemorySize, HG_SMEM);
    cudaFuncSetAttribute(attn9, cudaFuncAttributeMaxDynamicSharedMemorySize, ATT_SMEM);

    // 1) prep: activations -> fp16 (MLP=4); weight transposes (merged)
    const int actN4 = ROWS * D / 4;              // 1048576
    const int cvblocks = actN4 / (4 * 256);      // 1024
    cvth4<<<dim3(cvblocks, 2), 256>>>(pPA, (const float4*)patch,
                                      pPX, (const float4*)pixel,
                                      actN4, cvblocks * 256);
    transpose_cvt4<<<dim3(32, 32, 4), dim3(32, 8)>>>(pWQ, Wq, pWK, Wk, pWV, Wv, pWO, Wo);

    // 2) Q/K/V projections (one launch); Q scaled by scale*log2e
    dim3 ggrid(INNER / 128, ROWS / 128, 3);
    hgemm<true, true, false><<<ggrid, 256, HG_SMEM>>>(
        pPA, pWQ, pQ, pPX, pWK, pK, pPX, pWV, pV, nullptr, ROWS, INNER, D, SCALE_LOG2E);

    // 3) attention (single wave: 512 blocks, 4 blocks/SM)
    attn9<<<AGRID9, 128, ATT_SMEM>>>(pQ, pK, pV, pA);

    // 4) output projection + bias (fp32 out)
    dim3 ogrid(D / 128, ROWS / 128, 1);
    hgemm<false, false, true><<<ogrid, 256, HG_SMEM>>>(
        pA, pWO, out, nullptr, nullptr, nullptr, nullptr, nullptr, nullptr,
        bo, ROWS, D, INNER, 1.0f);
}

// round 14
// speedup vs baseline: 1.0265x; 1.0265x over previous
#include <cuda_runtime.h>
#include <cuda_fp16.h>
#include <math.h>
#include <stdint.h>

constexpr int B_    = 2;
constexpr int NQ    = 2048;
constexpr int NKV   = 2048;
constexpr int D     = 1024;
constexpr int INNER = 1024;
constexpr int HEADS = 16;
constexpr int DIMH  = 64;

constexpr int ROWS = B_ * NQ; // 4096
constexpr float SCALE_LOG2E = 0.125f * 1.4426950408889634f;

// Scratch (allocation-free rule: __device__ globals)
__device__ __half g_Q[ROWS * INNER];
__device__ __half g_K[ROWS * INNER];
__device__ __half g_V[ROWS * INNER];
__device__ __half g_A[ROWS * INNER];
__device__ __half g_PA[ROWS * D];
__device__ __half g_PX[ROWS * D];
__device__ __half g_WQ[D * INNER];   // transposed weights [N][K]
__device__ __half g_WK[D * INNER];
__device__ __half g_WV[D * INNER];
__device__ __half g_WO[INNER * D];

// ---------------------------------------------------------------------------
// helpers
// ---------------------------------------------------------------------------
__device__ __forceinline__ void cp_async16(void* dst, const void* src) {
    uint32_t s = (uint32_t)__cvta_generic_to_shared(dst);
    asm volatile("cp.async.cg.shared.global [%0], [%1], 16;\n" :: "r"(s), "l"(src));
}
__device__ __forceinline__ void cp_commit() { asm volatile("cp.async.commit_group;\n"); }

__device__ __forceinline__ float ex2(float x) {
    float r; asm("ex2.approx.ftz.f32 %0, %1;" : "=f"(r) : "f"(x)); return r;
}
__device__ __forceinline__ uint32_t pack2(float lo, float hi) {
    uint32_t r;
    asm("cvt.rn.f16x2.f32 %0, %1, %2;" : "=r"(r) : "f"(hi), "f"(lo));
    return r;
}

__device__ __forceinline__ void mma_f16(float* c, const uint32_t* a, uint32_t b0, uint32_t b1) {
    asm volatile(
        "mma.sync.aligned.m16n8k16.row.col.f32.f16.f16.f32 "
        "{%0,%1,%2,%3}, {%4,%5,%6,%7}, {%8,%9}, {%0,%1,%2,%3};\n"
        : "+f"(c[0]), "+f"(c[1]), "+f"(c[2]), "+f"(c[3])
        : "r"(a[0]), "r"(a[1]), "r"(a[2]), "r"(a[3]), "r"(b0), "r"(b1));
}

__device__ __forceinline__ void ldmx4(uint32_t& r0, uint32_t& r1, uint32_t& r2, uint32_t& r3,
                                      const void* p) {
    uint32_t a = (uint32_t)__cvta_generic_to_shared(p);
    asm volatile("ldmatrix.sync.aligned.m8n8.x4.shared.b16 {%0,%1,%2,%3}, [%4];"
                 : "=r"(r0), "=r"(r1), "=r"(r2), "=r"(r3) : "r"(a));
}
__device__ __forceinline__ void ldmx4_trans(uint32_t& r0, uint32_t& r1, uint32_t& r2, uint32_t& r3,
                                            const void* p) {
    uint32_t a = (uint32_t)__cvta_generic_to_shared(p);
    asm volatile("ldmatrix.sync.aligned.m8n8.x4.trans.shared.b16 {%0,%1,%2,%3}, [%4];"
                 : "=r"(r0), "=r"(r1), "=r"(r2), "=r"(r3) : "r"(a));
}
__device__ __forceinline__ void ldmx2_trans(uint32_t& r0, uint32_t& r1, const void* p) {
    uint32_t a = (uint32_t)__cvta_generic_to_shared(p);
    asm volatile("ldmatrix.sync.aligned.m8n8.x2.trans.shared.b16 {%0,%1}, [%2];"
                 : "=r"(r0), "=r"(r1) : "r"(a));
}

// ---------------------------------------------------------------------------
// prep kernels
// ---------------------------------------------------------------------------
__global__ void cvth4(__half* __restrict__ d0, const float4* __restrict__ s0,
                      __half* __restrict__ d1, const float4* __restrict__ s1,
                      int n4, int stride) {
    const int base = blockIdx.x * blockDim.x + threadIdx.x;
    const float4* s = blockIdx.y ? s1 : s0;
    __half* d = blockIdx.y ? d1 : d0;
    float4 v[4];
#pragma unroll
    for (int k = 0; k < 4; k++) {
        const int i = base + k * stride;
        v[k] = s[i];
    }
#pragma unroll
    for (int k = 0; k < 4; k++) {
        const int i = base + k * stride;
        uint2 o;
        o.x = pack2(v[k].x, v[k].y);
        o.y = pack2(v[k].z, v[k].w);
        *reinterpret_cast<uint2*>(d + 4 * (size_t)i) = o;
    }
}

__global__ void transpose_cvt4(__half* __restrict__ d0, const float* __restrict__ s0,
                               __half* __restrict__ d1, const float* __restrict__ s1,
                               __half* __restrict__ d2, const float* __restrict__ s2,
                               __half* __restrict__ d3, const float* __restrict__ s3) {
    __shared__ float t[32][33];
    const int z = blockIdx.z;
    const float* src = (z == 0) ? s0 : (z == 1) ? s1 : (z == 2) ? s2 : s3;
    __half* dst = (z == 0) ? d0 : (z == 1) ? d1 : (z == 2) ? d2 : d3;
    const int n0 = blockIdx.x * 32;
    const int k0 = blockIdx.y * 32;
    const int tx = threadIdx.x, ty = threadIdx.y;
#pragma unroll
    for (int i = 0; i < 4; i++)
        t[ty + i * 8][tx] = src[(size_t)(k0 + ty + i * 8) * 1024 + n0 + tx];
    __syncthreads();
#pragma unroll
    for (int i = 0; i < 4; i++)
        dst[(size_t)(n0 + ty + i * 8) * 1024 + k0 + tx] = __float2half_rn(t[tx][ty + i * 8]);
}

// ---------------------------------------------------------------------------
// fp16 GEMM v2: BM=256 x BN=128, BK=32 (high arithmetic intensity:
// 24KB loads per 2048 compute-cycles -> ~1.8 KB/cyc chip << LTS cap).
// 256 thr, 8 warps in 4x2, warp tile 64x64. 4-stage cp.async pipeline.
// ---------------------------------------------------------------------------
constexpr int HG_LD = 40;                          // halves per smem row (32+8)
constexpr int HG_ATILE = 256 * HG_LD;              // A-stage halves
constexpr int HG_BTILE = 128 * HG_LD;              // B-stage halves
constexpr int HG_STAGE = HG_ATILE + HG_BTILE;      // 15360 halves = 30720 B
constexpr int HG_STAGES = 4;
constexpr int HG_SMEM = HG_STAGES * HG_STAGE * 2;  // 122880 B

template <bool QKV, bool HALF_OUT, bool BIAS>
__global__ __launch_bounds__(256, 1)
void hgemm2(const __half* __restrict__ A0, const __half* __restrict__ W0, void* __restrict__ C0,
            const __half* __restrict__ A1, const __half* __restrict__ W1, void* __restrict__ C1,
            const __half* __restrict__ A2, const __half* __restrict__ W2, void* __restrict__ C2,
            const float* __restrict__ bias, int M, int N, int K, float oscale0) {
    extern __shared__ __half sh[];

    const __half* A = A0; const __half* WT = W0; void* Cv = C0;
    float oscale = oscale0;
    if (QKV) {
        const int z = blockIdx.z;
        if (z == 1) { A = A1; WT = W1; Cv = C1; oscale = 1.0f; }
        else if (z == 2) { A = A2; WT = W2; Cv = C2; oscale = 1.0f; }
    }

    const int tid  = threadIdx.x;
    const int wid  = tid >> 5;
    const int lane = tid & 31;
    const int g    = lane >> 2;
    const int tig  = lane & 3;
    const int wm = wid >> 1;      // 0..3 -> 64-row band
    const int wn = wid & 1;       // 0..1 -> 64-col band
    const int bm0 = blockIdx.y * 256;
    const int bn0 = blockIdx.x * 128;
    const int lmr = lane & 15;
    const int lmc = (lane >> 4) * 8;

    float acc[4][8][4];
#pragma unroll
    for (int mi = 0; mi < 4; mi++)
#pragma unroll
        for (int nb = 0; nb < 8; nb++)
#pragma unroll
            for (int e = 0; e < 4; e++) acc[mi][nb][e] = 0.0f;

    auto load_tiles = [&](int buf, int k0) {
        __half* As = sh + buf * HG_STAGE;
        __half* Bs = As + HG_ATILE;
        // A: 256 rows x 4 chunks = 1024 chunks / 256 thr = 4 each
#pragma unroll
        for (int i = 0; i < 4; i++) {
            const int idx = tid + i * 256;
            const int r = idx >> 2, c = idx & 3;
            cp_async16(&As[r * HG_LD + c * 8],
                       &A[(size_t)(bm0 + r) * K + k0 + c * 8]);
        }
        // B: 128 rows x 4 chunks = 512 chunks / 256 thr = 2 each
#pragma unroll
        for (int i = 0; i < 2; i++) {
            const int idx = tid + i * 256;
            const int r = idx >> 2, c = idx & 3;
            cp_async16(&Bs[r * HG_LD + c * 8],
                       &WT[(size_t)(bn0 + r) * K + k0 + c * 8]);
        }
    };

    const int KT = K / 32;
    load_tiles(0, 0);  cp_commit();
    load_tiles(1, 32); cp_commit();
    load_tiles(2, 64); cp_commit();

    for (int t = 0; t < KT; t++) {
        const int buf = t & 3;
        asm volatile("cp.async.wait_group 2;\n");
        __syncthreads();
        if (t + 3 < KT) { load_tiles((t + 3) & 3, (t + 3) * 32); cp_commit(); }

        const __half* Ab = sh + buf * HG_STAGE;
        const __half* Bb = Ab + HG_ATILE;
#pragma unroll
        for (int ks = 0; ks < 2; ks++) {
            uint32_t a[4][4];
            uint32_t b[4][4];
#pragma unroll
            for (int mi = 0; mi < 4; mi++)
                ldmx4(a[mi][0], a[mi][1], a[mi][2], a[mi][3],
                      Ab + (wm * 64 + mi * 16 + lmr) * HG_LD + ks * 16 + lmc);
#pragma unroll
            for (int nbp = 0; nbp < 4; nbp++)
                ldmx4(b[nbp][0], b[nbp][1], b[nbp][2], b[nbp][3],
                      Bb + (wn * 64 + nbp * 16 + lmr) * HG_LD + ks * 16 + lmc);
#pragma unroll
            for (int nbp = 0; nbp < 4; nbp++)
#pragma unroll
                for (int mi = 0; mi < 4; mi++) {
                    mma_f16(acc[mi][2 * nbp],     a[mi], b[nbp][0], b[nbp][2]);
                    mma_f16(acc[mi][2 * nbp + 1], a[mi], b[nbp][1], b[nbp][3]);
                }
        }
    }

    // epilogue
#pragma unroll
    for (int mi = 0; mi < 4; mi++) {
        const int row0 = bm0 + wm * 64 + mi * 16 + g;
#pragma unroll
        for (int nb = 0; nb < 8; nb++) {
            const int col = bn0 + wn * 64 + nb * 8 + 2 * tig;
            float c0 = acc[mi][nb][0] * oscale, c1 = acc[mi][nb][1] * oscale;
            float c2 = acc[mi][nb][2] * oscale, c3 = acc[mi][nb][3] * oscale;
            if (BIAS) {
                const float b0 = bias[col], b1 = bias[col + 1];
                c0 += b0; c1 += b1; c2 += b0; c3 += b1;
            }
            if (HALF_OUT) {
                __half* C = (__half*)Cv;
                *reinterpret_cast<uint32_t*>(&C[(size_t)row0 * N + col])       = pack2(c0, c1);
                *reinterpret_cast<uint32_t*>(&C[(size_t)(row0 + 8) * N + col]) = pack2(c2, c3);
            } else {
                float* C = (float*)Cv;
                *reinterpret_cast<float2*>(&C[(size_t)row0 * N + col])       = make_float2(c0, c1);
                *reinterpret_cast<float2*>(&C[(size_t)(row0 + 8) * N + col]) = make_float2(c2, c3);
            }
        }
    }
}

// ---------------------------------------------------------------------------
// fp16 flash attention (attn5, round-9 best: 103.6us): persistent-444,
// 4 warps x 32 q-rows, unnormalized fp32 ex2 softmax, ones-column mma sums.
// ---------------------------------------------------------------------------
constexpr int ALD = 72;                       // halves per K/V row (144B stride)
constexpr int ATILE = 64 * ALD;               // halves per tile
constexpr int ATT_SMEM = 2 * 2 * ATILE * 2;   // 36864 B
constexpr int AUNITS = (NQ / 128) * HEADS * B_;  // 512
constexpr int AGRID  = 148 * 3;                   // 444

__global__ __launch_bounds__(128, 3)
void attn5(const __half* __restrict__ Q, const __half* __restrict__ K,
           const __half* __restrict__ V, __half* __restrict__ O) {
    extern __shared__ __half sh[];

    const int tid  = threadIdx.x;
    const int w    = tid >> 5;
    const int lane = tid & 31;
    const int g    = lane >> 2;
    const int tig  = lane & 3;
    const int lmr = lane & 15;
    const int lmc = (lane >> 4) * 8;

    // ones-pad init: V tiles' cols 64-71 = [1,0,...] in both buffers
    {
        const int buf = tid >> 6, r = tid & 63;
        uint4 ones = make_uint4(0x00003C00u, 0u, 0u, 0u);
        *reinterpret_cast<uint4*>(sh + (buf * 2 + 1) * ATILE + r * ALD + 64) = ones;
    }

    auto prefetch = [&](const __half* Kg, const __half* Vg, int buf, int j0) {
#pragma unroll
        for (int i = 0; i < 4; i++) {
            const int idx = tid + i * 128;
            const int r = idx >> 3, c = idx & 7;
            cp_async16(&sh[buf * 2 * ATILE + r * ALD + c * 8],
                       Kg + (size_t)(j0 + r) * INNER + c * 8);
        }
#pragma unroll
        for (int i = 0; i < 4; i++) {
            const int idx = tid + i * 128;
            const int r = idx >> 3, c = idx & 7;
            cp_async16(&sh[buf * 2 * ATILE + ATILE + r * ALD + c * 8],
                       Vg + (size_t)(j0 + r) * INNER + c * 8);
        }
    };

    for (int u = blockIdx.x; u < AUNITS; u += AGRID) {
        const int qt = u & 15;
        const int hb = u >> 4;
        const int h  = hb & 15;
        const int b  = hb >> 4;
        const int q0 = qt * 128;

        const __half* Kg = K + (size_t)(b * NKV) * INNER + h * DIMH;
        const __half* Vg = V + (size_t)(b * NKV) * INNER + h * DIMH;

        uint32_t qa0[4][4], qa1[4][4];
        const int r0 = q0 + w * 32 + g;
        {
            const __half* Q0 = Q + (size_t)(b * NQ + r0) * INNER + h * DIMH;
            const __half* Q1 = Q0 + 8 * (size_t)INNER;
            const __half* Q2 = Q0 + 16 * (size_t)INNER;
            const __half* Q3 = Q0 + 24 * (size_t)INNER;
#pragma unroll
            for (int kk = 0; kk < 4; kk++) {
                qa0[kk][0] = *reinterpret_cast<const uint32_t*>(Q0 + kk * 16 + 2 * tig);
                qa0[kk][1] = *reinterpret_cast<const uint32_t*>(Q1 + kk * 16 + 2 * tig);
                qa0[kk][2] = *reinterpret_cast<const uint32_t*>(Q0 + kk * 16 + 2 * tig + 8);
                qa0[kk][3] = *reinterpret_cast<const uint32_t*>(Q1 + kk * 16 + 2 * tig + 8);
                qa1[kk][0] = *reinterpret_cast<const uint32_t*>(Q2 + kk * 16 + 2 * tig);
                qa1[kk][1] = *reinterpret_cast<const uint32_t*>(Q3 + kk * 16 + 2 * tig);
                qa1[kk][2] = *reinterpret_cast<const uint32_t*>(Q2 + kk * 16 + 2 * tig + 8);
                qa1[kk][3] = *reinterpret_cast<const uint32_t*>(Q3 + kk * 16 + 2 * tig + 8);
            }
        }

        float oa0[8][4], oa1[8][4];
        float sum0[4] = {0.f, 0.f, 0.f, 0.f};
        float sum1[4] = {0.f, 0.f, 0.f, 0.f};
#pragma unroll
        for (int nb = 0; nb < 8; nb++)
#pragma unroll
            for (int e = 0; e < 4; e++) { oa0[nb][e] = 0.0f; oa1[nb][e] = 0.0f; }

        prefetch(Kg, Vg, 0, 0);
        cp_commit();

        constexpr int NT = NKV / 64;
        for (int t = 0; t < NT; t++) {
            const int buf = t & 1;
            asm volatile("cp.async.wait_group 0;\n");
            __syncthreads();
            if (t + 1 < NT) { prefetch(Kg, Vg, buf ^ 1, (t + 1) * 64); cp_commit(); }

            const __half* Kb = sh + buf * 2 * ATILE;
            const __half* Vb = Kb + ATILE;

#pragma unroll
            for (int nbp = 0; nbp < 4; nbp++) {
                float s00[4] = {0.f,0.f,0.f,0.f}, s01[4] = {0.f,0.f,0.f,0.f};
                float s10[4] = {0.f,0.f,0.f,0.f}, s11[4] = {0.f,0.f,0.f,0.f};
#pragma unroll
                for (int kk = 0; kk < 4; kk++) {
                    uint32_t b0, b1, b2, b3;
                    ldmx4(b0, b1, b2, b3, Kb + (nbp * 16 + lmr) * ALD + kk * 16 + lmc);
                    mma_f16(s00, qa0[kk], b0, b2);
                    mma_f16(s01, qa0[kk], b1, b3);
                    mma_f16(s10, qa1[kk], b0, b2);
                    mma_f16(s11, qa1[kk], b1, b3);
                }
                uint32_t pa0[4], pa1[4];
                pa0[0] = pack2(ex2(s00[0]), ex2(s00[1]));
                pa0[1] = pack2(ex2(s00[2]), ex2(s00[3]));
                pa0[2] = pack2(ex2(s01[0]), ex2(s01[1]));
                pa0[3] = pack2(ex2(s01[2]), ex2(s01[3]));
                pa1[0] = pack2(ex2(s10[0]), ex2(s10[1]));
                pa1[1] = pack2(ex2(s10[2]), ex2(s10[3]));
                pa1[2] = pack2(ex2(s11[0]), ex2(s11[1]));
                pa1[3] = pack2(ex2(s11[2]), ex2(s11[3]));

#pragma unroll
                for (int j = 0; j < 4; j++) {
                    uint32_t b0, b1, b2, b3;
                    ldmx4_trans(b0, b1, b2, b3, Vb + (nbp * 16 + lmr) * ALD + j * 16 + lmc);
                    mma_f16(oa0[2 * j],     pa0, b0, b1);
                    mma_f16(oa0[2 * j + 1], pa0, b2, b3);
                    mma_f16(oa1[2 * j],     pa1, b0, b1);
                    mma_f16(oa1[2 * j + 1], pa1, b2, b3);
                }
                {
                    uint32_t c0, c1;
                    ldmx2_trans(c0, c1, Vb + (nbp * 16 + lmr) * ALD + 64);
                    mma_f16(sum0, pa0, c0, c1);
                    mma_f16(sum1, pa1, c0, c1);
                }
            }
        }

        const int src = lane & 28;
        const float inv00 = 1.0f / __shfl_sync(0xffffffffu, sum0[0], src);
        const float inv01 = 1.0f / __shfl_sync(0xffffffffu, sum0[2], src);
        const float inv10 = 1.0f / __shfl_sync(0xffffffffu, sum1[0], src);
        const float inv11 = 1.0f / __shfl_sync(0xffffffffu, sum1[2], src);

        __half* O0 = O + (size_t)(b * NQ + r0) * INNER + h * DIMH;
        __half* O1 = O0 + 8 * (size_t)INNER;
        __half* O2 = O0 + 16 * (size_t)INNER;
        __half* O3 = O0 + 24 * (size_t)INNER;
#pragma unroll
        for (int nb = 0; nb < 8; nb++) {
            *reinterpret_cast<uint32_t*>(O0 + nb * 8 + 2 * tig) =
                pack2(oa0[nb][0] * inv00, oa0[nb][1] * inv00);
            *reinterpret_cast<uint32_t*>(O1 + nb * 8 + 2 * tig) =
                pack2(oa0[nb][2] * inv01, oa0[nb][3] * inv01);
            *reinterpret_cast<uint32_t*>(O2 + nb * 8 + 2 * tig) =
                pack2(oa1[nb][0] * inv10, oa1[nb][1] * inv10);
            *reinterpret_cast<uint32_t*>(O3 + nb * 8 + 2 * tig) =
                pack2(oa1[nb][2] * inv11, oa1[nb][3] * inv11);
        }
    }
}

// ---------------------------------------------------------------------------
extern "C" void kernel_launch(void* const* d_in, const int* in_sizes, int n_in,
                              void* d_out, int out_size) {
    const float* patch = (const float*)d_in[0];
    const float* pixel = (const float*)d_in[1];
    const float* Wq    = (const float*)d_in[2];
    const float* Wk    = (const float*)d_in[3];
    const float* Wv    = (const float*)d_in[4];
    const float* Wo    = (const float*)d_in[5];
    const float* bo    = (const float*)d_in[6];
    float* out = (float*)d_out;

    __half *pQ, *pK, *pV, *pA, *pPA, *pPX, *pWQ, *pWK, *pWV, *pWO;
    cudaGetSymbolAddress((void**)&pQ,  g_Q);
    cudaGetSymbolAddress((void**)&pK,  g_K);
    cudaGetSymbolAddress((void**)&pV,  g_V);
    cudaGetSymbolAddress((void**)&pA,  g_A);
    cudaGetSymbolAddress((void**)&pPA, g_PA);
    cudaGetSymbolAddress((void**)&pPX, g_PX);
    cudaGetSymbolAddress((void**)&pWQ, g_WQ);
    cudaGetSymbolAddress((void**)&pWK, g_WK);
    cudaGetSymbolAddress((void**)&pWV, g_WV);
    cudaGetSymbolAddress((void**)&pWO, g_WO);

    cudaFuncSetAttribute((const void*)hgemm2<true, true, false>,
                         cudaFuncAttributeMaxDynamicSharedMemorySize, HG_SMEM);
    cudaFuncSetAttribute((const void*)hgemm2<false, false, true>,
                         cudaFuncAttributeMaxDynamicSharedMemorySize, HG_SMEM);
    cudaFuncSetAttribute(attn5, cudaFuncAttributeMaxDynamicSharedMemorySize, ATT_SMEM);

    // 1) prep: activations -> fp16 (MLP=4); weight transposes (merged)
    const int actN4 = ROWS * D / 4;              // 1048576
    const int cvblocks = actN4 / (4 * 256);      // 1024
    cvth4<<<dim3(cvblocks, 2), 256>>>(pPA, (const float4*)patch,
                                      pPX, (const float4*)pixel,
                                      actN4, cvblocks * 256);
    transpose_cvt4<<<dim3(32, 32, 4), dim3(32, 8)>>>(pWQ, Wq, pWK, Wk, pWV, Wv, pWO, Wo);

    // 2) Q/K/V projections (one launch); Q scaled by scale*log2e
    dim3 ggrid(INNER / 128, ROWS / 256, 3);      // (8, 16, 3) = 384 blocks
    hgemm2<true, true, false><<<ggrid, 256, HG_SMEM>>>(
        pPA, pWQ, pQ, pPX, pWK, pK, pPX, pWV, pV, nullptr, ROWS, INNER, D, SCALE_LOG2E);

    // 3) attention (persistent-444, round-9 best)
    attn5<<<AGRID, 128, ATT_SMEM>>>(pQ, pK, pV, pA);

    // 4) output projection + bias (fp32 out)
    dim3 ogrid(D / 128, ROWS / 256, 1);          // (8, 16) = 128 blocks
    hgemm2<false, false, true><<<ogrid, 256, HG_SMEM>>>(
        pA, pWO, out, nullptr, nullptr, nullptr, nullptr, nullptr, nullptr,
        bo, ROWS, D, INNER, 1.0f);
}

// round 15
// speedup vs baseline: 1.0743x; 1.0466x over previous
#include <cuda_runtime.h>
#include <cuda_fp16.h>
#include <math.h>
#include <stdint.h>

constexpr int B_    = 2;
constexpr int NQ    = 2048;
constexpr int NKV   = 2048;
constexpr int D     = 1024;
constexpr int INNER = 1024;
constexpr int HEADS = 16;
constexpr int DIMH  = 64;

constexpr int ROWS = B_ * NQ; // 4096
constexpr float SCALE_LOG2E = 0.125f * 1.4426950408889634f;

// Scratch (allocation-free rule: __device__ globals)
__device__ __half g_Q[ROWS * INNER];
__device__ __half g_K[ROWS * INNER];
__device__ __half g_V[ROWS * INNER];
__device__ __half g_A[ROWS * INNER];
__device__ __half g_PA[ROWS * D];
__device__ __half g_PX[ROWS * D];
__device__ __half g_WQ[D * INNER];   // transposed weights [N][K]
__device__ __half g_WK[D * INNER];
__device__ __half g_WV[D * INNER];
__device__ __half g_WO[INNER * D];

// ---------------------------------------------------------------------------
// helpers
// ---------------------------------------------------------------------------
__device__ __forceinline__ void cp_async16(void* dst, const void* src) {
    uint32_t s = (uint32_t)__cvta_generic_to_shared(dst);
    asm volatile("cp.async.cg.shared.global [%0], [%1], 16;\n" :: "r"(s), "l"(src));
}
__device__ __forceinline__ void cp_commit() { asm volatile("cp.async.commit_group;\n"); }

__device__ __forceinline__ float ex2(float x) {
    float r; asm("ex2.approx.ftz.f32 %0, %1;" : "=f"(r) : "f"(x)); return r;
}
__device__ __forceinline__ uint32_t pack2(float lo, float hi) {
    uint32_t r;
    asm("cvt.rn.f16x2.f32 %0, %1, %2;" : "=r"(r) : "f"(hi), "f"(lo));
    return r;
}

__device__ __forceinline__ void mma_f16(float* c, const uint32_t* a, uint32_t b0, uint32_t b1) {
    asm volatile(
        "mma.sync.aligned.m16n8k16.row.col.f32.f16.f16.f32 "
        "{%0,%1,%2,%3}, {%4,%5,%6,%7}, {%8,%9}, {%0,%1,%2,%3};\n"
        : "+f"(c[0]), "+f"(c[1]), "+f"(c[2]), "+f"(c[3])
        : "r"(a[0]), "r"(a[1]), "r"(a[2]), "r"(a[3]), "r"(b0), "r"(b1));
}

__device__ __forceinline__ void ldmx4(uint32_t& r0, uint32_t& r1, uint32_t& r2, uint32_t& r3,
                                      const void* p) {
    uint32_t a = (uint32_t)__cvta_generic_to_shared(p);
    asm volatile("ldmatrix.sync.aligned.m8n8.x4.shared.b16 {%0,%1,%2,%3}, [%4];"
                 : "=r"(r0), "=r"(r1), "=r"(r2), "=r"(r3) : "r"(a));
}
__device__ __forceinline__ void ldmx4_trans(uint32_t& r0, uint32_t& r1, uint32_t& r2, uint32_t& r3,
                                            const void* p) {
    uint32_t a = (uint32_t)__cvta_generic_to_shared(p);
    asm volatile("ldmatrix.sync.aligned.m8n8.x4.trans.shared.b16 {%0,%1,%2,%3}, [%4];"
                 : "=r"(r0), "=r"(r1), "=r"(r2), "=r"(r3) : "r"(a));
}
__device__ __forceinline__ void ldmx2_trans(uint32_t& r0, uint32_t& r1, const void* p) {
    uint32_t a = (uint32_t)__cvta_generic_to_shared(p);
    asm volatile("ldmatrix.sync.aligned.m8n8.x2.trans.shared.b16 {%0,%1}, [%2];"
                 : "=r"(r0), "=r"(r1) : "r"(a));
}

// ---------------------------------------------------------------------------
// prep kernels
// ---------------------------------------------------------------------------
__global__ void cvth4(__half* __restrict__ d0, const float4* __restrict__ s0,
                      __half* __restrict__ d1, const float4* __restrict__ s1,
                      int n4, int stride) {
    const int base = blockIdx.x * blockDim.x + threadIdx.x;
    const float4* s = blockIdx.y ? s1 : s0;
    __half* d = blockIdx.y ? d1 : d0;
    float4 v[4];
#pragma unroll
    for (int k = 0; k < 4; k++) {
        const int i = base + k * stride;
        v[k] = s[i];
    }
#pragma unroll
    for (int k = 0; k < 4; k++) {
        const int i = base + k * stride;
        uint2 o;
        o.x = pack2(v[k].x, v[k].y);
        o.y = pack2(v[k].z, v[k].w);
        *reinterpret_cast<uint2*>(d + 4 * (size_t)i) = o;
    }
}

__global__ void transpose_cvt4(__half* __restrict__ d0, const float* __restrict__ s0,
                               __half* __restrict__ d1, const float* __restrict__ s1,
                               __half* __restrict__ d2, const float* __restrict__ s2,
                               __half* __restrict__ d3, const float* __restrict__ s3) {
    __shared__ float t[32][33];
    const int z = blockIdx.z;
    const float* src = (z == 0) ? s0 : (z == 1) ? s1 : (z == 2) ? s2 : s3;
    __half* dst = (z == 0) ? d0 : (z == 1) ? d1 : (z == 2) ? d2 : d3;
    const int n0 = blockIdx.x * 32;
    const int k0 = blockIdx.y * 32;
    const int tx = threadIdx.x, ty = threadIdx.y;
#pragma unroll
    for (int i = 0; i < 4; i++)
        t[ty + i * 8][tx] = src[(size_t)(k0 + ty + i * 8) * 1024 + n0 + tx];
    __syncthreads();
#pragma unroll
    for (int i = 0; i < 4; i++)
        dst[(size_t)(n0 + ty + i * 8) * 1024 + k0 + tx] = __float2half_rn(t[tx][ty + i * 8]);
}

// ---------------------------------------------------------------------------
// fp16 GEMM (round-9 best, unchanged): BM=BN=128, BK=32, 4-stage cp.async,
// 256 thr, 8 warps 4x2, warp tile 32x64, ldmatrix frag loads, 2 blocks/SM.
// ---------------------------------------------------------------------------
constexpr int HG_LD = 40;
constexpr int HG_TILE = 128 * HG_LD;
constexpr int HG_STAGES = 4;
constexpr int HG_SMEM = HG_STAGES * 2 * HG_TILE * 2; // 81920 B

template <bool QKV, bool HALF_OUT, bool BIAS>
__global__ __launch_bounds__(256, 2)
void hgemm(const __half* __restrict__ A0, const __half* __restrict__ W0, void* __restrict__ C0,
           const __half* __restrict__ A1, const __half* __restrict__ W1, void* __restrict__ C1,
           const __half* __restrict__ A2, const __half* __restrict__ W2, void* __restrict__ C2,
           const float* __restrict__ bias, int M, int N, int K, float oscale0) {
    extern __shared__ __half sh[];

    const __half* A = A0; const __half* WT = W0; void* Cv = C0;
    float oscale = oscale0;
    if (QKV) {
        const int z = blockIdx.z;
        if (z == 1) { A = A1; WT = W1; Cv = C1; oscale = 1.0f; }
        else if (z == 2) { A = A2; WT = W2; Cv = C2; oscale = 1.0f; }
    }

    const int tid  = threadIdx.x;
    const int wid  = tid >> 5;
    const int lane = tid & 31;
    const int g    = lane >> 2;
    const int tig  = lane & 3;
    const int wm = wid >> 1;
    const int wn = wid & 1;
    const int bm0 = blockIdx.y * 128;
    const int bn0 = blockIdx.x * 128;
    const int lmr = lane & 15;
    const int lmc = (lane >> 4) * 8;

    float acc[2][8][4];
#pragma unroll
    for (int mi = 0; mi < 2; mi++)
#pragma unroll
        for (int nb = 0; nb < 8; nb++)
#pragma unroll
            for (int e = 0; e < 4; e++) acc[mi][nb][e] = 0.0f;

    auto load_tiles = [&](int buf, int k0) {
#pragma unroll
        for (int i = 0; i < 2; i++) {
            const int idx = tid + i * 256;
            const int r = idx >> 2, c = idx & 3;
            cp_async16(&sh[buf * 2 * HG_TILE + r * HG_LD + c * 8],
                       &A[(size_t)(bm0 + r) * K + k0 + c * 8]);
        }
#pragma unroll
        for (int i = 0; i < 2; i++) {
            const int idx = tid + i * 256;
            const int r = idx >> 2, c = idx & 3;
            cp_async16(&sh[buf * 2 * HG_TILE + HG_TILE + r * HG_LD + c * 8],
                       &WT[(size_t)(bn0 + r) * K + k0 + c * 8]);
        }
    };

    const int KT = K / 32;
    load_tiles(0, 0);  cp_commit();
    load_tiles(1, 32); cp_commit();
    load_tiles(2, 64); cp_commit();

    for (int t = 0; t < KT; t++) {
        const int buf = t & 3;
        asm volatile("cp.async.wait_group 2;\n");
        __syncthreads();
        if (t + 3 < KT) { load_tiles((t + 3) & 3, (t + 3) * 32); cp_commit(); }

        const __half* Ab = sh + buf * 2 * HG_TILE;
        const __half* Bb = Ab + HG_TILE;
#pragma unroll
        for (int ks = 0; ks < 2; ks++) {
            uint32_t a[2][4];
            uint32_t b[4][4];
#pragma unroll
            for (int mi = 0; mi < 2; mi++)
                ldmx4(a[mi][0], a[mi][1], a[mi][2], a[mi][3],
                      Ab + (wm * 32 + mi * 16 + lmr) * HG_LD + ks * 16 + lmc);
#pragma unroll
            for (int nbp = 0; nbp < 4; nbp++)
                ldmx4(b[nbp][0], b[nbp][1], b[nbp][2], b[nbp][3],
                      Bb + (wn * 64 + nbp * 16 + lmr) * HG_LD + ks * 16 + lmc);
#pragma unroll
            for (int nbp = 0; nbp < 4; nbp++)
#pragma unroll
                for (int mi = 0; mi < 2; mi++) {
                    mma_f16(acc[mi][2 * nbp],     a[mi], b[nbp][0], b[nbp][2]);
                    mma_f16(acc[mi][2 * nbp + 1], a[mi], b[nbp][1], b[nbp][3]);
                }
        }
    }

#pragma unroll
    for (int mi = 0; mi < 2; mi++) {
        const int row0 = bm0 + wm * 32 + mi * 16 + g;
#pragma unroll
        for (int nb = 0; nb < 8; nb++) {
            const int col = bn0 + wn * 64 + nb * 8 + 2 * tig;
            float c0 = acc[mi][nb][0] * oscale, c1 = acc[mi][nb][1] * oscale;
            float c2 = acc[mi][nb][2] * oscale, c3 = acc[mi][nb][3] * oscale;
            if (BIAS) {
                const float b0 = bias[col], b1 = bias[col + 1];
                c0 += b0; c1 += b1; c2 += b0; c3 += b1;
            }
            if (HALF_OUT) {
                __half* C = (__half*)Cv;
                *reinterpret_cast<uint32_t*>(&C[(size_t)row0 * N + col])       = pack2(c0, c1);
                *reinterpret_cast<uint32_t*>(&C[(size_t)(row0 + 8) * N + col]) = pack2(c2, c3);
            } else {
                float* C = (float*)Cv;
                *reinterpret_cast<float2*>(&C[(size_t)row0 * N + col])       = make_float2(c0, c1);
                *reinterpret_cast<float2*>(&C[(size_t)(row0 + 8) * N + col]) = make_float2(c2, c3);
            }
        }
    }
}

// ---------------------------------------------------------------------------
// fp16 flash attention v10 = attn5 (persistent-444, 4 warps x 32 q-rows,
// unnormalized fp32 ex2 softmax, ones-column mma row sums) with kv-tile 128:
// halves per-tile sync/wait serialization and doubles independent unrolled
// chunks per tile (8 nbp). smem 73.7KB x 3 blocks = 221KB <= 228 -> occ 3.
// ---------------------------------------------------------------------------
constexpr int ALD = 72;                       // halves per K/V row (144B stride)
constexpr int AKV = 128;                      // kv rows per tile
constexpr int ATILE = AKV * ALD;              // halves per K or V tile
constexpr int ATT_SMEM = 2 * 2 * ATILE * 2;   // 73728 B
constexpr int AUNITS = (NQ / 128) * HEADS * B_;  // 512
constexpr int AGRID  = 148 * 3;                   // 444

__global__ __launch_bounds__(128, 3)
void attn10(const __half* __restrict__ Q, const __half* __restrict__ K,
            const __half* __restrict__ V, __half* __restrict__ O) {
    extern __shared__ __half sh[];

    const int tid  = threadIdx.x;
    const int w    = tid >> 5;
    const int lane = tid & 31;
    const int g    = lane >> 2;
    const int tig  = lane & 3;
    const int lmr = lane & 15;
    const int lmc = (lane >> 4) * 8;

    // ones-pad init: V tiles' cols 64-71 = [1,0,...] in both buffers (128 rows each)
#pragma unroll
    for (int i = 0; i < 2; i++) {
        const int idx = tid + i * 128;          // 0..255 covers 2 bufs x 128 rows
        const int buf = idx >> 7, r = idx & 127;
        uint4 ones = make_uint4(0x00003C00u, 0u, 0u, 0u);
        *reinterpret_cast<uint4*>(sh + (buf * 2 + 1) * ATILE + r * ALD + 64) = ones;
    }

    auto prefetch = [&](const __half* Kg, const __half* Vg, int buf, int j0) {
#pragma unroll
        for (int i = 0; i < 8; i++) {
            const int idx = tid + i * 128;
            const int r = idx >> 3, c = idx & 7;
            cp_async16(&sh[buf * 2 * ATILE + r * ALD + c * 8],
                       Kg + (size_t)(j0 + r) * INNER + c * 8);
        }
#pragma unroll
        for (int i = 0; i < 8; i++) {
            const int idx = tid + i * 128;
            const int r = idx >> 3, c = idx & 7;
            cp_async16(&sh[buf * 2 * ATILE + ATILE + r * ALD + c * 8],
                       Vg + (size_t)(j0 + r) * INNER + c * 8);
        }
    };

    for (int u = blockIdx.x; u < AUNITS; u += AGRID) {
        const int qt = u & 15;
        const int hb = u >> 4;
        const int h  = hb & 15;
        const int b  = hb >> 4;
        const int q0 = qt * 128;

        const __half* Kg = K + (size_t)(b * NKV) * INNER + h * DIMH;
        const __half* Vg = V + (size_t)(b * NKV) * INNER + h * DIMH;

        uint32_t qa0[4][4], qa1[4][4];
        const int r0 = q0 + w * 32 + g;
        {
            const __half* Q0 = Q + (size_t)(b * NQ + r0) * INNER + h * DIMH;
            const __half* Q1 = Q0 + 8 * (size_t)INNER;
            const __half* Q2 = Q0 + 16 * (size_t)INNER;
            const __half* Q3 = Q0 + 24 * (size_t)INNER;
#pragma unroll
            for (int kk = 0; kk < 4; kk++) {
                qa0[kk][0] = *reinterpret_cast<const uint32_t*>(Q0 + kk * 16 + 2 * tig);
                qa0[kk][1] = *reinterpret_cast<const uint32_t*>(Q1 + kk * 16 + 2 * tig);
                qa0[kk][2] = *reinterpret_cast<const uint32_t*>(Q0 + kk * 16 + 2 * tig + 8);
                qa0[kk][3] = *reinterpret_cast<const uint32_t*>(Q1 + kk * 16 + 2 * tig + 8);
                qa1[kk][0] = *reinterpret_cast<const uint32_t*>(Q2 + kk * 16 + 2 * tig);
                qa1[kk][1] = *reinterpret_cast<const uint32_t*>(Q3 + kk * 16 + 2 * tig);
                qa1[kk][2] = *reinterpret_cast<const uint32_t*>(Q2 + kk * 16 + 2 * tig + 8);
                qa1[kk][3] = *reinterpret_cast<const uint32_t*>(Q3 + kk * 16 + 2 * tig + 8);
            }
        }

        float oa0[8][4], oa1[8][4];
        float sum0[4] = {0.f, 0.f, 0.f, 0.f};
        float sum1[4] = {0.f, 0.f, 0.f, 0.f};
#pragma unroll
        for (int nb = 0; nb < 8; nb++)
#pragma unroll
            for (int e = 0; e < 4; e++) { oa0[nb][e] = 0.0f; oa1[nb][e] = 0.0f; }

        prefetch(Kg, Vg, 0, 0);
        cp_commit();

        constexpr int NT = NKV / AKV;   // 16
        for (int t = 0; t < NT; t++) {
            const int buf = t & 1;
            asm volatile("cp.async.wait_group 0;\n");
            __syncthreads();
            if (t + 1 < NT) { prefetch(Kg, Vg, buf ^ 1, (t + 1) * AKV); cp_commit(); }

            const __half* Kb = sh + buf * 2 * ATILE;
            const __half* Vb = Kb + ATILE;

#pragma unroll
            for (int nbp = 0; nbp < 8; nbp++) {
                float s00[4] = {0.f,0.f,0.f,0.f}, s01[4] = {0.f,0.f,0.f,0.f};
                float s10[4] = {0.f,0.f,0.f,0.f}, s11[4] = {0.f,0.f,0.f,0.f};
#pragma unroll
                for (int kk = 0; kk < 4; kk++) {
                    uint32_t b0, b1, b2, b3;
                    ldmx4(b0, b1, b2, b3, Kb + (nbp * 16 + lmr) * ALD + kk * 16 + lmc);
                    mma_f16(s00, qa0[kk], b0, b2);
                    mma_f16(s01, qa0[kk], b1, b3);
                    mma_f16(s10, qa1[kk], b0, b2);
                    mma_f16(s11, qa1[kk], b1, b3);
                }
                uint32_t pa0[4], pa1[4];
                pa0[0] = pack2(ex2(s00[0]), ex2(s00[1]));
                pa0[1] = pack2(ex2(s00[2]), ex2(s00[3]));
                pa0[2] = pack2(ex2(s01[0]), ex2(s01[1]));
                pa0[3] = pack2(ex2(s01[2]), ex2(s01[3]));
                pa1[0] = pack2(ex2(s10[0]), ex2(s10[1]));
                pa1[1] = pack2(ex2(s10[2]), ex2(s10[3]));
                pa1[2] = pack2(ex2(s11[0]), ex2(s11[1]));
                pa1[3] = pack2(ex2(s11[2]), ex2(s11[3]));

#pragma unroll
                for (int j = 0; j < 4; j++) {
                    uint32_t b0, b1, b2, b3;
                    ldmx4_trans(b0, b1, b2, b3, Vb + (nbp * 16 + lmr) * ALD + j * 16 + lmc);
                    mma_f16(oa0[2 * j],     pa0, b0, b1);
                    mma_f16(oa0[2 * j + 1], pa0, b2, b3);
                    mma_f16(oa1[2 * j],     pa1, b0, b1);
                    mma_f16(oa1[2 * j + 1], pa1, b2, b3);
                }
                {
                    uint32_t c0, c1;
                    ldmx2_trans(c0, c1, Vb + (nbp * 16 + lmr) * ALD + 64);
                    mma_f16(sum0, pa0, c0, c1);
                    mma_f16(sum1, pa1, c0, c1);
                }
            }
        }

        const int src = lane & 28;
        const float inv00 = 1.0f / __shfl_sync(0xffffffffu, sum0[0], src);
        const float inv01 = 1.0f / __shfl_sync(0xffffffffu, sum0[2], src);
        const float inv10 = 1.0f / __shfl_sync(0xffffffffu, sum1[0], src);
        const float inv11 = 1.0f / __shfl_sync(0xffffffffu, sum1[2], src);

        __half* O0 = O + (size_t)(b * NQ + r0) * INNER + h * DIMH;
        __half* O1 = O0 + 8 * (size_t)INNER;
        __half* O2 = O0 + 16 * (size_t)INNER;
        __half* O3 = O0 + 24 * (size_t)INNER;
#pragma unroll
        for (int nb = 0; nb < 8; nb++) {
            *reinterpret_cast<uint32_t*>(O0 + nb * 8 + 2 * tig) =
                pack2(oa0[nb][0] * inv00, oa0[nb][1] * inv00);
            *reinterpret_cast<uint32_t*>(O1 + nb * 8 + 2 * tig) =
                pack2(oa0[nb][2] * inv01, oa0[nb][3] * inv01);
            *reinterpret_cast<uint32_t*>(O2 + nb * 8 + 2 * tig) =
                pack2(oa1[nb][0] * inv10, oa1[nb][1] * inv10);
            *reinterpret_cast<uint32_t*>(O3 + nb * 8 + 2 * tig) =
                pack2(oa1[nb][2] * inv11, oa1[nb][3] * inv11);
        }
    }
}

// ---------------------------------------------------------------------------
extern "C" void kernel_launch(void* const* d_in, const int* in_sizes, int n_in,
                              void* d_out, int out_size) {
    const float* patch = (const float*)d_in[0];
    const float* pixel = (const float*)d_in[1];
    const float* Wq    = (const float*)d_in[2];
    const float* Wk    = (const float*)d_in[3];
    const float* Wv    = (const float*)d_in[4];
    const float* Wo    = (const float*)d_in[5];
    const float* bo    = (const float*)d_in[6];
    float* out = (float*)d_out;

    __half *pQ, *pK, *pV, *pA, *pPA, *pPX, *pWQ, *pWK, *pWV, *pWO;
    cudaGetSymbolAddress((void**)&pQ,  g_Q);
    cudaGetSymbolAddress((void**)&pK,  g_K);
    cudaGetSymbolAddress((void**)&pV,  g_V);
    cudaGetSymbolAddress((void**)&pA,  g_A);
    cudaGetSymbolAddress((void**)&pPA, g_PA);
    cudaGetSymbolAddress((void**)&pPX, g_PX);
    cudaGetSymbolAddress((void**)&pWQ, g_WQ);
    cudaGetSymbolAddress((void**)&pWK, g_WK);
    cudaGetSymbolAddress((void**)&pWV, g_WV);
    cudaGetSymbolAddress((void**)&pWO, g_WO);

    cudaFuncSetAttribute((const void*)hgemm<true, true, false>,
                         cudaFuncAttributeMaxDynamicSharedMemorySize, HG_SMEM);
    cudaFuncSetAttribute((const void*)hgemm<false, false, true>,
                         cudaFuncAttributeMaxDynamicSharedMemorySize, HG_SMEM);
    cudaFuncSetAttribute(attn10, cudaFuncAttributeMaxDynamicSharedMemorySize, ATT_SMEM);

    // 1) prep: activations -> fp16 (MLP=4); weight transposes (merged)
    const int actN4 = ROWS * D / 4;              // 1048576
    const int cvblocks = actN4 / (4 * 256);      // 1024
    cvth4<<<dim3(cvblocks, 2), 256>>>(pPA, (const float4*)patch,
                                      pPX, (const float4*)pixel,
                                      actN4, cvblocks * 256);
    transpose_cvt4<<<dim3(32, 32, 4), dim3(32, 8)>>>(pWQ, Wq, pWK, Wk, pWV, Wv, pWO, Wo);

    // 2) Q/K/V projections (one launch); Q scaled by scale*log2e
    dim3 ggrid(INNER / 128, ROWS / 128, 3);      // (8, 32, 3) = 768 blocks
    hgemm<true, true, false><<<ggrid, 256, HG_SMEM>>>(
        pPA, pWQ, pQ, pPX, pWK, pK, pPX, pWV, pV, nullptr, ROWS, INNER, D, SCALE_LOG2E);

    // 3) attention (persistent-444, kv-tile 128)
    attn10<<<AGRID, 128, ATT_SMEM>>>(pQ, pK, pV, pA);

    // 4) output projection + bias (fp32 out)
    dim3 ogrid(D / 128, ROWS / 128, 1);          // (8, 32) = 256 blocks
    hgemm<false, false, true><<<ogrid, 256, HG_SMEM>>>(
        pA, pWO, out, nullptr, nullptr, nullptr, nullptr, nullptr, nullptr,
        bo, ROWS, D, INNER, 1.0f);
}